// round 17
// baseline (speedup 1.0000x reference)
#include <cuda_runtime.h>
#include <cuda_fp16.h>
#include <math.h>

#define Bc   8
#define Nc   325
#define Tc   24
#define Dc   64
#define Hc   8
#define Mc   16
#define E2c  128
#define BNc  2600   // Bc*Nc

// ---------------- device scratch ----------------
__device__ float g_tfeat[Bc * Mc];                            // (B,16)
__device__ float g_gcn[(size_t)Bc * Nc * Tc * Dc];            // (B,N,T,D) ~16MB
__device__ __align__(16) __half g_weff[(size_t)3 * BNc * E2c * E2c]; // fp16 ~256MB
__device__ __align__(16) __half g_wh[(size_t)3 * Mc * E2c * E2c];    // fp16 QKV W 1.5MB
__device__ __align__(16) __half g_outw_h[E2c * Dc];           // fp16 out_w 128x64
__device__ __align__(16) __half g_gatew_h[E2c * Dc];          // fp16 gate_w 128x64

__device__ __forceinline__ float lrelu(float x) { return x > 0.f ? x : 0.1f * x; }

#define CP_ASYNC16(sdst, gsrc) \
    asm volatile("cp.async.cg.shared.global [%0], [%1], 16;" :: "r"(sdst), "l"(gsrc) : "memory")
#define CP_COMMIT() asm volatile("cp.async.commit_group;" ::: "memory")
#define CP_WAIT1()  asm volatile("cp.async.wait_group 1;" ::: "memory")
#define CP_WAIT0()  asm volatile("cp.async.wait_group 0;" ::: "memory")

__device__ __forceinline__ void ldsm_x4(unsigned* r, unsigned addr) {
    asm volatile("ldmatrix.sync.aligned.m8n8.x4.shared.b16 {%0,%1,%2,%3}, [%4];"
                 : "=r"(r[0]), "=r"(r[1]), "=r"(r[2]), "=r"(r[3]) : "r"(addr));
}
__device__ __forceinline__ void ldsm_x4_t(unsigned* r, unsigned addr) {
    asm volatile("ldmatrix.sync.aligned.m8n8.x4.trans.shared.b16 {%0,%1,%2,%3}, [%4];"
                 : "=r"(r[0]), "=r"(r[1]), "=r"(r[2]), "=r"(r[3]) : "r"(addr));
}
__device__ __forceinline__ void mma16816(float* c, const unsigned* a, unsigned b0, unsigned b1) {
    asm volatile("mma.sync.aligned.m16n8k16.row.col.f32.f16.f16.f32 "
                 "{%0,%1,%2,%3}, {%4,%5,%6,%7}, {%8,%9}, {%0,%1,%2,%3};"
                 : "+f"(c[0]), "+f"(c[1]), "+f"(c[2]), "+f"(c[3])
                 : "r"(a[0]), "r"(a[1]), "r"(a[2]), "r"(a[3]), "r"(b0), "r"(b1));
}
__device__ __forceinline__ unsigned packh2(float a, float b) {
    __half2 h = __floats2half2_rn(a, b);
    return *reinterpret_cast<unsigned*>(&h);
}

// ---------------- Kernel 0a: fp16 epilogue weight prep ----------------
__global__ void k_prep(const float* __restrict__ ow, const float* __restrict__ gw) {
    int i = blockIdx.x * 256 + threadIdx.x;   // grid 32 x 256 = 8192
    g_outw_h[i]  = __float2half(ow[i]);
    g_gatew_h[i] = __float2half(gw[i]);
}

// ---------------- Kernel 0b: fp16 QKV weight prep ----------------
__global__ void k_prepw(const float* __restrict__ WQ, const float* __restrict__ WK,
                        const float* __restrict__ WV) {
    int X = blockIdx.y;
    const float* W = (X == 0) ? WQ : (X == 1) ? WK : WV;
    int e = (blockIdx.x * 256 + threadIdx.x) * 4;   // 256 blocks x 256 th x 4 = 262144
    float4 v = *(const float4*)&W[e];
    __half2* dst = (__half2*)&g_wh[(size_t)X * 262144 + e];
    dst[0] = __floats2half2_rn(v.x, v.y);
    dst[1] = __floats2half2_rn(v.z, v.w);
}

// ---------------- Kernel 1: tfeat ----------------
__global__ void k_tfeat(const float* __restrict__ tXin,
                        const float* __restrict__ tpw,
                        const float* __restrict__ tpb) {
    __shared__ float s_mean[Dc];
    int b = blockIdx.x;
    int d = threadIdx.x;  // 64 threads
    const float* p = tXin + (size_t)b * Nc * Tc * Dc;  // n = 0 slice
    float s = 0.f;
    #pragma unroll
    for (int t = 0; t < Tc; t++) s += p[t * Dc + d];
    s_mean[d] = s * (1.0f / Tc);
    __syncthreads();
    if (d < Mc) {
        float acc = tpb[d];
        #pragma unroll
        for (int i = 0; i < Dc; i++) acc += s_mean[i] * tpw[i * Mc + d];
        g_tfeat[b * Mc + d] = tanhf(acc);
    }
}

// ---------------- Kernel 2: support GEMM + GCN, tensor cores --------------------
__global__ __launch_bounds__(256) void k_gcn(const float* __restrict__ matrix,
                                             const float* __restrict__ hidden,
                                             const float* __restrict__ gcn_w,
                                             const float* __restrict__ gcn_b) {
    __shared__ __half sA[64][40];
    __shared__ __half sB[32][72];
    __shared__ __half sS[64][72];
    __shared__ __half sW[64][72];
    int tid = threadIdx.x, lane = tid & 31, warp = tid >> 5;
    int nt = blockIdx.x, t = blockIdx.y, b = blockIdx.z;
    int n0 = nt * 64;

    for (int idx = tid; idx < 4096; idx += 256)
        sW[idx >> 6][idx & 63] = __float2half(gcn_w[idx]);

    const float* Mrow = matrix + ((size_t)(b * Tc + t) * Nc) * Nc;

    unsigned sA_b = (unsigned)__cvta_generic_to_shared(&sA[0][0]);
    unsigned sB_b = (unsigned)__cvta_generic_to_shared(&sB[0][0]);
    unsigned sS_b = (unsigned)__cvta_generic_to_shared(&sS[0][0]);
    unsigned sW_b = (unsigned)__cvta_generic_to_shared(&sW[0][0]);

    int r0 = (warp >> 1) * 16;
    int c0 = (warp & 1) * 32;
    int arow = (lane & 7) + (lane & 8);
    int acol8 = (lane & 16) ? 8 : 0;
    int trow = lane >> 2, p2 = lane & 3;

    float acc[4][4] = {};
    for (int kc = 0; kc < 11; kc++) {
        int m0 = kc * 32;
        __syncthreads();
        for (int idx = tid; idx < 2048; idx += 256) {
            int i = idx >> 5, j = idx & 31;
            int n = n0 + i, m = m0 + j;
            float v = (n < Nc && m < Nc) ? Mrow[(size_t)n * Nc + m] : 0.f;
            sA[i][j] = __float2half(v);
        }
        for (int idx = tid; idx < 2048; idx += 256) {
            int j = idx >> 6, d = idx & 63;
            int m = m0 + j;
            float v = (m < Nc) ? hidden[((size_t)(b * Nc + m) * Tc + t) * Dc + d] : 0.f;
            sB[j][d] = __float2half(v);
        }
        __syncthreads();
        #pragma unroll
        for (int ks = 0; ks < 2; ks++) {
            unsigned af[4], bf0[4], bf1[4];
            ldsm_x4(af,    sA_b + ((r0 + arow) * 40 + ks * 16 + acol8) * 2);
            ldsm_x4_t(bf0, sB_b + ((ks * 16 + arow) * 72 + c0 + acol8) * 2);
            ldsm_x4_t(bf1, sB_b + ((ks * 16 + arow) * 72 + c0 + 16 + acol8) * 2);
            mma16816(acc[0], af, bf0[0], bf0[1]);
            mma16816(acc[1], af, bf0[2], bf0[3]);
            mma16816(acc[2], af, bf1[0], bf1[1]);
            mma16816(acc[3], af, bf1[2], bf1[3]);
        }
    }

    #pragma unroll
    for (int ntile = 0; ntile < 4; ntile++) {
        int col = c0 + ntile * 8 + 2 * p2;
        *(__half2*)&sS[r0 + trow][col]     = __floats2half2_rn(acc[ntile][0], acc[ntile][1]);
        *(__half2*)&sS[r0 + trow + 8][col] = __floats2half2_rn(acc[ntile][2], acc[ntile][3]);
    }
    __syncthreads();

    float acc2[4][4] = {};
    #pragma unroll
    for (int ks = 0; ks < 4; ks++) {
        unsigned af[4], bf0[4], bf1[4];
        ldsm_x4(af,    sS_b + ((r0 + arow) * 72 + ks * 16 + acol8) * 2);
        ldsm_x4_t(bf0, sW_b + ((ks * 16 + arow) * 72 + c0 + acol8) * 2);
        ldsm_x4_t(bf1, sW_b + ((ks * 16 + arow) * 72 + c0 + 16 + acol8) * 2);
        mma16816(acc2[0], af, bf0[0], bf0[1]);
        mma16816(acc2[1], af, bf0[2], bf0[3]);
        mma16816(acc2[2], af, bf1[0], bf1[1]);
        mma16816(acc2[3], af, bf1[2], bf1[3]);
    }

    #pragma unroll
    for (int ntile = 0; ntile < 4; ntile++) {
        int col = c0 + ntile * 8 + 2 * p2;
        float bx = gcn_b[col], by = gcn_b[col + 1];
        int n1 = n0 + r0 + trow, n2 = n1 + 8;
        if (n1 < Nc) {
            float2 o = make_float2(fmaxf(acc2[ntile][0] + bx, 0.f),
                                   fmaxf(acc2[ntile][1] + by, 0.f));
            *(float2*)&g_gcn[((size_t)(b * Nc + n1) * Tc + t) * Dc + col] = o;
        }
        if (n2 < Nc) {
            float2 o = make_float2(fmaxf(acc2[ntile][2] + bx, 0.f),
                                   fmaxf(acc2[ntile][3] + by, 0.f));
            *(float2*)&g_gcn[((size_t)(b * Nc + n2) * Tc + t) * Dc + col] = o;
        }
    }
}

// ---------------- Kernel 3: Weff build, tensor cores + wide stores --------------
// Block: 64 bn x 256 cols. Warp: 16 bn x 128 cols (tw = warp>>1, ch = warp&1).
__global__ __launch_bounds__(256) void k_weff(const float* __restrict__ node_emb) {
    __shared__ __half s_w[16][264];        // 16 k x 256 n (+8 pad), rows 528B
    __shared__ __half s_emb[64][24];       // 64 bn x 16 m (+8 pad)
    __shared__ __half s_o[8][16][136];     // per-warp 16 x 128 (+8 pad)
    int tid = threadIdx.x, lane = tid & 31, warp = tid >> 5;
    int cx = blockIdx.x;   // 64 chunks of 256 cols
    int by = blockIdx.y;   // 41 groups of 64 bn rows
    int X  = blockIdx.z;

    unsigned sw_b = (unsigned)__cvta_generic_to_shared(&s_w[0][0]);

    // stage W fp16 via cp.async: 16 rows x 512B = 512 x 16B transfers
    {
        const __half* src = g_wh + (size_t)X * 262144 + cx * 256;
        #pragma unroll
        for (int rep = 0; rep < 2; rep++) {
            int i = tid + rep * 256;
            int r = i >> 5, s = i & 31;
            CP_ASYNC16(sw_b + r * 528 + s * 16, src + r * 16384 + s * 8);
        }
        CP_COMMIT();
    }
    // stage emb fp16 (zero for bn >= BNc)
    for (int i = tid; i < 1024; i += 256) {
        int row = i >> 4, m = i & 15;
        int bn = by * 64 + row;
        float e = 0.f;
        if (bn < BNc) {
            int b = bn / Nc, n = bn - b * Nc;
            e = node_emb[n * Mc + m] * g_tfeat[b * Mc + m];
        }
        s_emb[row][m] = __float2half(e);
    }
    CP_WAIT0();
    __syncthreads();

    int tw = warp >> 1, ch = warp & 1;
    int arow = (lane & 7) + (lane & 8);
    int acol = (lane & 16) ? 8 : 0;
    unsigned emb_b = (unsigned)__cvta_generic_to_shared(&s_emb[0][0]);

    unsigned aF[4];
    ldsm_x4(aF, emb_b + ((tw * 16 + arow) * 24 + acol) * 2);

    int trow = lane >> 2, p2 = lane & 3;
    __half(*so)[136] = s_o[warp];

    #pragma unroll
    for (int it = 0; it < 8; it++) {
        unsigned bF[4];
        ldsm_x4_t(bF, sw_b + (arow * 264 + ch * 128 + it * 16 + acol) * 2);
        float c0[4] = {}, c1[4] = {};
        mma16816(c0, aF, bF[0], bF[1]);
        mma16816(c1, aF, bF[2], bF[3]);
        int colo = it * 16 + 2 * p2;
        *(__half2*)&so[trow][colo]         = __floats2half2_rn(c0[0], c0[1]);
        *(__half2*)&so[trow][colo + 8]     = __floats2half2_rn(c1[0], c1[1]);
        *(__half2*)&so[trow + 8][colo]     = __floats2half2_rn(c0[2], c0[3]);
        *(__half2*)&so[trow + 8][colo + 8] = __floats2half2_rn(c1[2], c1[3]);
    }
    __syncwarp();

    // coalesced STG.128: 2 lanes per row, 8 float4 per lane
    int r = lane >> 1, seg = lane & 1;
    int bn_r = by * 64 + tw * 16 + r;
    if (bn_r < BNc) {
        __half* og = g_weff + ((size_t)X * BNc + bn_r) * 16384 + cx * 256 + ch * 128;
        #pragma unroll
        for (int j = 0; j < 4; j++) {
            int col = (seg * 4 + j) * 16;   // 16 halfs per float4-pair step
            *(float4*)&og[col]     = *(const float4*)&so[r][col];
            *(float4*)&og[col + 8] = *(const float4*)&so[r][col + 8];
        }
    }
}

// ---------------- Kernel 4: fused per-(b,n) attention path (round-15, passing) --
#define ATTN_SMEM_FLOATS 10752
#define ATTN_SMEM_BYTES  (ATTN_SMEM_FLOATS * 4)

__global__ __launch_bounds__(256, 4) void k_attn(const float* __restrict__ hidden,
                                                 const float* __restrict__ tXin,
                                                 const float* __restrict__ out_b,
                                                 const float* __restrict__ gate_b,
                                                 float* __restrict__ out) {
    extern __shared__ float sm[];
    __half* s_act   = (__half*)sm;              // 32x136 halfs
    __half* s_qh    = (__half*)(sm + 4224);
    __half* s_kh    = (__half*)(sm + 6400);
    __half* s_vh    = (__half*)(sm + 8576);
    __half* s_valh  = s_act;                    // overlay (epilogue)
    __half* s_gateh = s_qh;                     // overlay (epilogue) [gcn | value]

    int tid  = threadIdx.x;
    int lane = tid & 31;
    int warp = tid >> 5;
    int bn   = blockIdx.x;
    size_t base = (size_t)bn * (Tc * Dc);

    for (int idx = tid; idx < 4096; idx += 256) {
        int t = idx >> 7, i = idx & 127;
        float vv = 0.f;
        if (t < Tc) vv = (i < 64) ? hidden[base + t * 64 + i] : tXin[base + t * 64 + (i - 64)];
        s_act[t * 136 + i] = __float2half(vv);
    }

    const __half* wq = g_weff + (size_t)bn * 16384;
    const __half* wk = g_weff + ((size_t)BNc + bn) * 16384;
    const __half* wv = g_weff + ((size_t)2 * BNc + bn) * 16384;

    unsigned act_base = (unsigned)__cvta_generic_to_shared(s_act);
    unsigned wp_base  = act_base + 2176 * 4 + warp * 1024;
    unsigned swb      = act_base + 2176 * 4;

    int wn = warp * 16;
    int wl_r = lane >> 1, wl_c = lane & 1;
    unsigned wdst_off = wl_r * 32 + wl_c * 16;
    int wsrc_off = wl_r * 128 + wn + wl_c * 8;

    CP_ASYNC16(wp_base + wdst_off, wq + wsrc_off);
    CP_COMMIT();

    int arow = (lane & 7) + (lane & 8);
    int acol = (lane & 16) ? 8 : 0;
    unsigned a_off0 = (arow * 136 + acol) * 2;
    unsigned a_off1 = ((16 + arow) * 136 + acol) * 2;
    unsigned wb_off = arow * 32 + acol * 2;

    int trow = lane >> 2, tcol = (lane & 3) * 2;
    int p2 = lane & 3, ql = lane >> 2;

    __syncthreads();

    int buf = 0;
    for (int X = 0; X < 3; X++) {
        float acc[2][2][4] = {};
        for (int kk = 0; kk < 8; kk++) {
            int s = X * 8 + kk;
            if (s < 23) {
                int s1 = s + 1;
                int X1 = s1 >> 3, i0 = (s1 & 7) * 16;
                const __half* w = (X1 == 0) ? wq : (X1 == 1) ? wk : wv;
                CP_ASYNC16(wp_base + (buf ^ 1) * 512 + wdst_off, w + i0 * 128 + wsrc_off);
                CP_COMMIT();
                CP_WAIT1();
            } else {
                CP_WAIT0();
            }
            __syncwarp();

            unsigned a0f[4], a1f[4], bf[4];
            ldsm_x4(a0f, act_base + a_off0 + kk * 32);
            ldsm_x4(a1f, act_base + a_off1 + kk * 32);
            ldsm_x4_t(bf, wp_base + buf * 512 + wb_off);
            mma16816(acc[0][0], a0f, bf[0], bf[1]);
            mma16816(acc[0][1], a1f, bf[0], bf[1]);
            mma16816(acc[1][0], a0f, bf[2], bf[3]);
            mma16816(acc[1][1], a1f, bf[2], bf[3]);

            buf ^= 1;
        }
        __half* dst = (X == 0) ? s_qh : (X == 1) ? s_kh : s_vh;
        #pragma unroll
        for (int nt = 0; nt < 2; nt++) {
            int colb = wn + nt * 8 + tcol;
            float* c0p = acc[nt][0];
            *(__half2*)&dst[trow * 136 + colb] = __floats2half2_rn(lrelu(c0p[0]), lrelu(c0p[1]));
            *(__half2*)&dst[(trow + 8) * 136 + colb] = __floats2half2_rn(lrelu(c0p[2]), lrelu(c0p[3]));
            float* c1p = acc[nt][1];
            *(__half2*)&dst[(16 + trow) * 136 + colb] = __floats2half2_rn(lrelu(c1p[0]), lrelu(c1p[1]));
        }
    }

    __syncthreads();

    // ================= warp-local attention: head h = warp ======================
    float val[2][2][4] = {};
    {
        int h = warp;
        {
            int zr = 24 + (lane >> 2);
            int cu = (lane & 3) * 2;
            unsigned* vz = (unsigned*)s_vh;
            vz[zr * 68 + h * 8 + cu]     = 0u;
            vz[zr * 68 + h * 8 + cu + 1] = 0u;
        }
        __syncwarp();

        unsigned qh_base = act_base + 4224 * 4;
        unsigned kh_base = act_base + 6400 * 4;
        unsigned vh_base = act_base + 8576 * 4;
        unsigned hcol_off = (arow * 136 + h * 16 + acol) * 2;

        unsigned kq0[4], kq1[4], kb0[4], kb1[4];
        ldsm_x4(kq0, qh_base + hcol_off);
        ldsm_x4(kq1, qh_base + hcol_off + 16 * 272);
        ldsm_x4(kb0, kh_base + hcol_off);
        ldsm_x4(kb1, kh_base + hcol_off + 16 * 272);

        float sc[2][3][4] = {};
        mma16816(sc[0][0], kq0, kb0[0], kb0[2]);
        mma16816(sc[0][1], kq0, kb0[1], kb0[3]);
        mma16816(sc[0][2], kq0, kb1[0], kb1[2]);
        mma16816(sc[1][0], kq1, kb0[0], kb0[2]);
        mma16816(sc[1][1], kq1, kb0[1], kb0[3]);
        mma16816(sc[1][2], kq1, kb1[0], kb1[2]);

        unsigned ah[3][3];
        #pragma unroll
        for (int g = 0; g < 3; g++) {
            int t = ql + 8 * g;
            float x[6];
            #pragma unroll
            for (int nt = 0; nt < 3; nt++) {
                #pragma unroll
                for (int p = 0; p < 2; p++) {
                    float raw = (g == 0) ? sc[0][nt][p]
                              : (g == 1) ? sc[0][nt][2 + p]
                                         : sc[1][nt][p];
                    int scol = nt * 8 + 2 * p2 + p;
                    x[nt * 2 + p] = (scol <= t) ? 0.25f * raw : -1e30f;
                }
            }
            float mx = x[0];
            #pragma unroll
            for (int j = 1; j < 6; j++) mx = fmaxf(mx, x[j]);
            mx = fmaxf(mx, __shfl_xor_sync(0xFFFFFFFF, mx, 1));
            mx = fmaxf(mx, __shfl_xor_sync(0xFFFFFFFF, mx, 2));
            float e[6], sum = 0.f;
            #pragma unroll
            for (int j = 0; j < 6; j++) { e[j] = __expf(x[j] - mx); sum += e[j]; }
            sum += __shfl_xor_sync(0xFFFFFFFF, sum, 1);
            sum += __shfl_xor_sync(0xFFFFFFFF, sum, 2);
            float inv = 1.f / sum;
            #pragma unroll
            for (int nt = 0; nt < 3; nt++)
                ah[g][nt] = packh2(e[nt * 2] * inv, e[nt * 2 + 1] * inv);
        }

        unsigned vb0[4], vb1[4];
        ldsm_x4_t(vb0, vh_base + hcol_off);
        ldsm_x4_t(vb1, vh_base + hcol_off + 16 * 272);

        unsigned A00[4] = { ah[0][0], ah[1][0], ah[0][1], ah[1][1] };
        unsigned A01[4] = { ah[2][0], 0u,       ah[2][1], 0u       };
        unsigned A10[4] = { ah[0][2], ah[1][2], 0u,       0u       };
        unsigned A11[4] = { ah[2][2], 0u,       0u,       0u       };

        #pragma unroll
        for (int ne = 0; ne < 2; ne++) {
            mma16816(val[0][ne], A00, vb0[2 * ne], vb0[2 * ne + 1]);
            mma16816(val[0][ne], A10, vb1[2 * ne], vb1[2 * ne + 1]);
            mma16816(val[1][ne], A01, vb0[2 * ne], vb0[2 * ne + 1]);
            mma16816(val[1][ne], A11, vb1[2 * ne], vb1[2 * ne + 1]);
        }

        {
            int zr = 24 + (lane >> 2);
            int zc = (lane & 3) * 4;
            *(float2*)&s_valh[zr * 136 + h * 16 + zc] = make_float2(0.f, 0.f);
        }
        #pragma unroll
        for (int ne = 0; ne < 2; ne++) {
            int colf = h * 16 + ne * 8 + 2 * p2;
            *(__half2*)&s_valh[ql * 136 + colf]        = __floats2half2_rn(val[0][ne][0], val[0][ne][1]);
            *(__half2*)&s_valh[(ql + 8) * 136 + colf]  = __floats2half2_rn(val[0][ne][2], val[0][ne][3]);
            *(__half2*)&s_valh[(16 + ql) * 136 + colf] = __floats2half2_rn(val[1][ne][0], val[1][ne][1]);
        }
    }

    __syncthreads();

    for (int idx = tid; idx < 1536; idx += 256) {
        int t = idx >> 6, d = idx & 63;
        s_gateh[t * 136 + d] = __float2half(g_gcn[base + idx]);
    }
    for (int idx = tid; idx < 1024; idx += 256) {
        int r = 24 + (idx >> 7), c = idx & 127;
        s_gateh[r * 136 + c] = __float2half(0.f);
    }

    // ================= epilogue on tensor cores =================================
    int mg = warp >> 2, ng = warp & 3;
    unsigned aV_off = ((mg * 16 + arow) * 136 + acol) * 2;
    unsigned bW_off = (arow * 72 + ng * 16 + acol) * 2;
    int st_r = tid >> 3, st_s = tid & 7;
    unsigned st_dst = st_r * 144 + st_s * 16;
    int st_src = st_r * 64 + st_s * 8;

    if (tid < 128) CP_ASYNC16(swb + st_dst, g_outw_h + st_src);
    CP_COMMIT();

    float vacc[2][4] = {};
    int ebuf = 0;
    for (int kk = 0; kk < 8; kk++) {
        if (kk < 7) {
            if (tid < 128) CP_ASYNC16(swb + (ebuf ^ 1) * 2304 + st_dst,
                                      g_outw_h + (kk + 1) * 1024 + st_src);
            CP_COMMIT();
            CP_WAIT1();
        } else {
            CP_WAIT0();
        }
        __syncthreads();
        unsigned aF[4], bF[4];
        ldsm_x4(aF, act_base + aV_off + kk * 32);
        ldsm_x4_t(bF, swb + ebuf * 2304 + bW_off);
        mma16816(vacc[0], aF, bF[0], bF[1]);
        mma16816(vacc[1], aF, bF[2], bF[3]);
        __syncthreads();
        ebuf ^= 1;
    }

    float vv_[2][4];
    #pragma unroll
    for (int nt = 0; nt < 2; nt++) {
        int col = ng * 16 + nt * 8 + 2 * p2;
        float bx = out_b[col], by = out_b[col + 1];
        vv_[nt][0] = lrelu(vacc[nt][0] + bx);
        vv_[nt][1] = lrelu(vacc[nt][1] + by);
        vv_[nt][2] = lrelu(vacc[nt][2] + bx);
        vv_[nt][3] = lrelu(vacc[nt][3] + by);
        int r0a = mg * 16 + trow;
        int r1a = r0a + 8;
        *(__half2*)&s_gateh[r0a * 136 + 64 + col] = __floats2half2_rn(vv_[nt][0], vv_[nt][1]);
        if (mg == 0)
            *(__half2*)&s_gateh[r1a * 136 + 64 + col] = __floats2half2_rn(vv_[nt][2], vv_[nt][3]);
    }
    __syncthreads();

    if (tid < 128) CP_ASYNC16(swb + st_dst, g_gatew_h + st_src);
    CP_COMMIT();

    float gacc[2][4] = {};
    ebuf = 0;
    for (int kk = 0; kk < 8; kk++) {
        if (kk < 7) {
            if (tid < 128) CP_ASYNC16(swb + (ebuf ^ 1) * 2304 + st_dst,
                                      g_gatew_h + (kk + 1) * 1024 + st_src);
            CP_COMMIT();
            CP_WAIT1();
        } else {
            CP_WAIT0();
        }
        __syncthreads();
        unsigned aF[4], bF[4];
        ldsm_x4(aF, act_base + 4224 * 4 + aV_off + kk * 32);   // s_gateh
        ldsm_x4_t(bF, swb + ebuf * 2304 + bW_off);
        mma16816(gacc[0], aF, bF[0], bF[1]);
        mma16816(gacc[1], aF, bF[2], bF[3]);
        __syncthreads();
        ebuf ^= 1;
    }

    #pragma unroll
    for (int nt = 0; nt < 2; nt++) {
        int col = ng * 16 + nt * 8 + 2 * p2;
        float bgx = gate_b[col], bgy = gate_b[col + 1];
        int r0a = mg * 16 + trow;
        {
            float zx = 1.f / (1.f + __expf(-(gacc[nt][0] + bgx)));
            float zy = 1.f / (1.f + __expf(-(gacc[nt][1] + bgy)));
            float2 gc = __half22float2(*(__half2*)&s_gateh[r0a * 136 + col]);
            float2 hd = *(const float2*)&hidden[base + r0a * 64 + col];
            float2 o;
            o.x = zx * gc.x + (1.f - zx) * vv_[nt][0] + hd.x;
            o.y = zy * gc.y + (1.f - zy) * vv_[nt][1] + hd.y;
            *(float2*)&out[base + r0a * 64 + col] = o;
        }
        if (mg == 0) {
            int r1a = r0a + 8;
            float zx = 1.f / (1.f + __expf(-(gacc[nt][2] + bgx)));
            float zy = 1.f / (1.f + __expf(-(gacc[nt][3] + bgy)));
            float2 gc = __half22float2(*(__half2*)&s_gateh[r1a * 136 + col]);
            float2 hd = *(const float2*)&hidden[base + r1a * 64 + col];
            float2 o;
            o.x = zx * gc.x + (1.f - zx) * vv_[nt][2] + hd.x;
            o.y = zy * gc.y + (1.f - zy) * vv_[nt][3] + hd.y;
            *(float2*)&out[base + r1a * 64 + col] = o;
        }
    }
}

// ---------------- launch ----------------
extern "C" void kernel_launch(void* const* d_in, const int* in_sizes, int n_in,
                              void* d_out, int out_size) {
    const float* hidden   = (const float*)d_in[0];
    const float* tXin     = (const float*)d_in[1];
    const float* matrix   = (const float*)d_in[2];
    const float* gcn_w    = (const float*)d_in[3];
    const float* gcn_b    = (const float*)d_in[4];
    const float* node_emb = (const float*)d_in[5];
    const float* tproj_w  = (const float*)d_in[6];
    const float* tproj_b  = (const float*)d_in[7];
    const float* WK       = (const float*)d_in[8];
    const float* WQ       = (const float*)d_in[9];
    const float* WV       = (const float*)d_in[10];
    const float* out_w    = (const float*)d_in[11];
    const float* out_b    = (const float*)d_in[12];
    const float* gate_w   = (const float*)d_in[13];
    const float* gate_b   = (const float*)d_in[14];
    float* out = (float*)d_out;

    cudaFuncSetAttribute(k_attn, cudaFuncAttributeMaxDynamicSharedMemorySize, ATTN_SMEM_BYTES);

    k_tfeat<<<Bc, 64>>>(tXin, tproj_w, tproj_b);
    k_prep<<<32, 256>>>(out_w, gate_w);
    k_prepw<<<dim3(256, 3), 256>>>(WQ, WK, WV);
    k_gcn<<<dim3(6, Tc, Bc), 256>>>(matrix, hidden, gcn_w, gcn_b);
    k_weff<<<dim3(64, 41, 3), 256>>>(node_emb);
    k_attn<<<BNc, 256, ATTN_SMEM_BYTES>>>(hidden, tXin, out_b, gate_b, out);
}